// round 1
// baseline (speedup 1.0000x reference)
#include <cuda_runtime.h>
#include <cuda_bf16.h>

// ---------------------------------------------------------------------------
// GraphSAGE: out = normalize( [x | segsum(vals * x[cols])] @ W^T + b )
// N=100000 nodes, E=1600000 edges, IN_F=OUT_F=128. rows are sorted.
//
// Plan:
//   K1: zero neighbor scratch (51.2 MB __device__ global)
//   K2: SpMM — warp processes a contiguous 64-edge chunk; since rows are
//       sorted, keep a running float4 accumulator per lane and flush with a
//       vector atomicAdd only on row change (~5 flushes / 64 edges).
//       x fits in L2 (51 MB < 126 MB) -> gather is L2-bound (~75us floor).
//   K3: fused GEMM(256->128) + bias + row L2-normalize, fp32 with packed
//       fma.rn.f32x2 (2x FFMA throughput on sm_103a).
// ---------------------------------------------------------------------------

#define NNODES   100000
#define INF      128
#define TWOK     256
#define OUTF     128

__device__ float g_neighbor[(size_t)NNODES * INF];

// ---------------------------------------------------------------------------
// K1: zero scratch
// ---------------------------------------------------------------------------
__global__ void zero_kernel(int n4) {
    int i = blockIdx.x * blockDim.x + threadIdx.x;
    float4 z = make_float4(0.f, 0.f, 0.f, 0.f);
    if (i < n4) reinterpret_cast<float4*>(g_neighbor)[i] = z;
}

// ---------------------------------------------------------------------------
// K2: SpMM with sorted rows. One warp per 64-edge chunk, lane l owns feature
// dims [4l, 4l+4). Flush accumulator via float4 atomicAdd on row change.
// ---------------------------------------------------------------------------
#define EPW 64

__device__ __forceinline__ void flush_row(int row, int lane, float4 acc) {
    float4* nb4 = reinterpret_cast<float4*>(g_neighbor);
    atomicAdd(&nb4[(size_t)row * 32 + lane], acc);   // RED.128 on sm_90+
}

__global__ void spmm_kernel(const float* __restrict__ x,
                            const int*   __restrict__ rows,
                            const int*   __restrict__ cols,
                            const float* __restrict__ vals,
                            int E) {
    int warp = (blockIdx.x * blockDim.x + threadIdx.x) >> 5;
    int lane = threadIdx.x & 31;
    long base = (long)warp * EPW;
    if (base >= E) return;
    int n = (int)min((long)EPW, (long)E - base);

    const float4* x4 = reinterpret_cast<const float4*>(x);

    int cur = __ldg(rows + base);
    float4 acc = make_float4(0.f, 0.f, 0.f, 0.f);

    #pragma unroll 4
    for (int i = 0; i < n; i++) {
        long e = base + i;
        int   r = __ldg(rows + e);
        int   c = __ldg(cols + e);
        float v = __ldg(vals + e);
        if (r != cur) {                      // warp-uniform branch
            flush_row(cur, lane, acc);
            acc = make_float4(0.f, 0.f, 0.f, 0.f);
            cur = r;
        }
        float4 xv = x4[(size_t)c * 32 + lane];
        acc.x = fmaf(v, xv.x, acc.x);
        acc.y = fmaf(v, xv.y, acc.y);
        acc.z = fmaf(v, xv.z, acc.z);
        acc.w = fmaf(v, xv.w, acc.w);
    }
    flush_row(cur, lane, acc);
}

// ---------------------------------------------------------------------------
// K3: fused GEMM + bias + L2 normalize.
//   block = 256 threads, tile = 128 rows x 128 cols (all outputs).
//   tx = lane (col group: cols 4tx..4tx+3), ty = warp (rows ty*16..ty*16+15).
//   Wt in smem transposed [k][col], stride 132 (float4-aligned, low conflict).
//   A staged per 16-k chunk as duplicated float2 (a,a) so a single broadcast
//   LDS.64 feeds fma.rn.f32x2 directly. 32 FFMA2 / k / thread -> FMA-bound.
// ---------------------------------------------------------------------------
#define WPAD 132
#define APAD 129
#define KC   16
#define GEMM_SMEM_BYTES (TWOK * WPAD * 4 + KC * APAD * 8)

__device__ __forceinline__ unsigned long long pack2(float lo, float hi) {
    unsigned long long r;
    asm("mov.b64 %0, {%1, %2};" : "=l"(r) : "f"(lo), "f"(hi));
    return r;
}
__device__ __forceinline__ float2 unpack2(unsigned long long v) {
    float2 f;
    asm("mov.b64 {%0, %1}, %2;" : "=f"(f.x), "=f"(f.y) : "l"(v));
    return f;
}
#define FMA2(d, a, b, c) \
    asm("fma.rn.f32x2 %0, %1, %2, %3;" : "=l"(d) : "l"(a), "l"(b), "l"(c))

__global__ void __launch_bounds__(256, 1)
gemm_norm_kernel(const float* __restrict__ x,
                 const float* __restrict__ W,   // [128][256] row-major
                 const float* __restrict__ b,   // [128]
                 float* __restrict__ out,
                 int N) {
    extern __shared__ float smem[];
    float* Wt = smem;                                   // [256][WPAD]
    unsigned long long* Ad =
        reinterpret_cast<unsigned long long*>(smem + TWOK * WPAD); // [KC][APAD]

    int t  = threadIdx.x;
    int tx = t & 31;       // col group
    int ty = t >> 5;       // row group (warp)
    int rowBase = blockIdx.x * 128;
    int myRow0  = rowBase + ty * 16;

    // Load W transposed: thread t owns k = t, walks all 128 cols.
    // Read W[j*256 + t] (coalesced across t), write Wt[t*WPAD + j].
    #pragma unroll 4
    for (int j = 0; j < OUTF; j++)
        Wt[t * WPAD + j] = __ldg(W + j * TWOK + t);

    // Bias -> accumulator init (packed pairs).
    float4 bb = *reinterpret_cast<const float4*>(b + 4 * tx);
    unsigned long long a01[16], a23[16];
    {
        unsigned long long b01 = pack2(bb.x, bb.y);
        unsigned long long b23 = pack2(bb.z, bb.w);
        #pragma unroll
        for (int r = 0; r < 16; r++) { a01[r] = b01; a23[r] = b23; }
    }

    // K loop in chunks of KC=16.
    int arow = t >> 1;            // 0..127
    int koff = (t & 1) * 8;       // 0 or 8
    int gr   = rowBase + arow;

    for (int kc = 0; kc < TWOK; kc += KC) {
        __syncthreads();   // prev compute done reading Ad (also covers W load)

        // Stage A chunk: 8 consecutive k values for one row, duplicated.
        {
            int kg = kc + koff;
            float4 v0, v1;
            if (gr < N) {
                const float* src = (kg < INF)
                    ? (x + (size_t)gr * INF + kg)
                    : (g_neighbor + (size_t)gr * INF + (kg - INF));
                v0 = *reinterpret_cast<const float4*>(src);
                v1 = *reinterpret_cast<const float4*>(src + 4);
            } else {
                v0 = make_float4(0.f, 0.f, 0.f, 0.f);
                v1 = v0;
            }
            Ad[(koff + 0) * APAD + arow] = pack2(v0.x, v0.x);
            Ad[(koff + 1) * APAD + arow] = pack2(v0.y, v0.y);
            Ad[(koff + 2) * APAD + arow] = pack2(v0.z, v0.z);
            Ad[(koff + 3) * APAD + arow] = pack2(v0.w, v0.w);
            Ad[(koff + 4) * APAD + arow] = pack2(v1.x, v1.x);
            Ad[(koff + 5) * APAD + arow] = pack2(v1.y, v1.y);
            Ad[(koff + 6) * APAD + arow] = pack2(v1.z, v1.z);
            Ad[(koff + 7) * APAD + arow] = pack2(v1.w, v1.w);
        }
        __syncthreads();

        // Compute: for each k, 1x LDS128 (W) + 16x broadcast LDS64 (A) + 32 FFMA2.
        #pragma unroll
        for (int kl = 0; kl < KC; kl++) {
            int k = kc + kl;
            float4 w = *reinterpret_cast<const float4*>(Wt + k * WPAD + 4 * tx);
            unsigned long long w01 = pack2(w.x, w.y);
            unsigned long long w23 = pack2(w.z, w.w);
            const unsigned long long* arowp = Ad + kl * APAD + ty * 16;
            #pragma unroll
            for (int r = 0; r < 16; r++) {
                unsigned long long aa = arowp[r];
                FMA2(a01[r], aa, w01, a01[r]);
                FMA2(a23[r], aa, w23, a23[r]);
            }
        }
    }

    // Epilogue: per-row L2 normalize (row's 128 cols live across this warp).
    float4* out4 = reinterpret_cast<float4*>(out);
    #pragma unroll
    for (int r = 0; r < 16; r++) {
        int row = myRow0 + r;
        float2 c01 = unpack2(a01[r]);
        float2 c23 = unpack2(a23[r]);
        float s = c01.x * c01.x + c01.y * c01.y + c23.x * c23.x + c23.y * c23.y;
        #pragma unroll
        for (int off = 16; off >= 1; off >>= 1)
            s += __shfl_xor_sync(0xffffffffu, s, off);
        float nrm   = sqrtf(s);
        float scale = 1.0f / fmaxf(nrm, 1e-12f);
        if (row < N) {
            float4 o = make_float4(c01.x * scale, c01.y * scale,
                                   c23.x * scale, c23.y * scale);
            out4[(size_t)row * 32 + tx] = o;
        }
    }
}

// ---------------------------------------------------------------------------
// Launch
// ---------------------------------------------------------------------------
extern "C" void kernel_launch(void* const* d_in, const int* in_sizes, int n_in,
                              void* d_out, int out_size) {
    const float* x    = (const float*)d_in[0];
    const int*   rows = (const int*)  d_in[1];
    const int*   cols = (const int*)  d_in[2];
    const float* vals = (const float*)d_in[3];
    const float* W    = (const float*)d_in[4];
    const float* b    = (const float*)d_in[5];
    float*       out  = (float*)d_out;

    int N = in_sizes[0] / INF;
    int E = in_sizes[1];

    cudaFuncSetAttribute(gemm_norm_kernel,
                         cudaFuncAttributeMaxDynamicSharedMemorySize,
                         GEMM_SMEM_BYTES);

    // K1: zero neighbor scratch
    int n4 = N * (INF / 4);
    zero_kernel<<<(n4 + 255) / 256, 256>>>(n4);

    // K2: SpMM
    int warps  = (E + EPW - 1) / EPW;
    int blocks = (warps * 32 + 255) / 256;
    spmm_kernel<<<blocks, 256>>>(x, rows, cols, vals, E);

    // K3: fused GEMM + bias + normalize
    gemm_norm_kernel<<<(N + 127) / 128, 256, GEMM_SMEM_BYTES>>>(x, W, b, out, N);
}

// round 3
// speedup vs baseline: 1.9365x; 1.9365x over previous
#include <cuda_runtime.h>
#include <cuda_bf16.h>
#include <cstdint>

// ---------------------------------------------------------------------------
// GraphSAGE: out = normalize( [x | segsum(vals * x[cols])] @ W^T + b )
// N=100000, E=1600000, IN_F=OUT_F=128, rows sorted.
//
//   K1: zero neighbor scratch
//   K2: SpMM — coalesced edge loads + shfl broadcast; float4 atomic flush on
//       row change (rows sorted).
//   K3: mma.sync (HMMA) bf16-split GEMM (Ahi*Bhi + Alo*Bhi + Ahi*Blo ~ fp32)
//       fused with bias + row L2-normalize. tcgen05 unavailable: harness
//       ptxas targets plain sm_103 (no 'a' features).
// ---------------------------------------------------------------------------

#define NNODES   100000
#define INF      128
#define TWOK     256
#define OUTF     128

__device__ float g_neighbor[(size_t)NNODES * INF];

// ---------------------------------------------------------------------------
// K1: zero scratch
// ---------------------------------------------------------------------------
__global__ void zero_kernel(int n4) {
    int i = blockIdx.x * blockDim.x + threadIdx.x;
    if (i < n4)
        reinterpret_cast<float4*>(g_neighbor)[i] = make_float4(0.f, 0.f, 0.f, 0.f);
}

// ---------------------------------------------------------------------------
// K2: SpMM. Warp handles 32 edges: lane l loads edge (base+l) coalesced,
// then 32 shfl-broadcast steps; lane owns feature dims [4l, 4l+4).
// ---------------------------------------------------------------------------
__global__ void spmm_kernel(const float* __restrict__ x,
                            const int*   __restrict__ rows,
                            const int*   __restrict__ cols,
                            const float* __restrict__ vals,
                            int E) {
    int warp = (blockIdx.x * blockDim.x + threadIdx.x) >> 5;
    int lane = threadIdx.x & 31;
    long base = (long)warp * 32;
    if (base >= E) return;

    long e = base + lane;
    bool valid = e < E;
    long es = valid ? e : (long)E - 1;
    int   r = __ldg(rows + es);
    int   c = valid ? __ldg(cols + e) : 0;
    float v = valid ? __ldg(vals + e) : 0.f;

    const float4* x4  = reinterpret_cast<const float4*>(x);
    float4*       nb4 = reinterpret_cast<float4*>(g_neighbor);

    int cur = __shfl_sync(0xffffffffu, r, 0);
    float4 acc = make_float4(0.f, 0.f, 0.f, 0.f);

    #pragma unroll
    for (int j = 0; j < 32; j++) {
        int   rj = __shfl_sync(0xffffffffu, r, j);
        int   cj = __shfl_sync(0xffffffffu, c, j);
        float vj = __shfl_sync(0xffffffffu, v, j);
        float4 xv = x4[(size_t)cj * 32 + lane];
        if (rj != cur) {                       // warp-uniform
            atomicAdd(&nb4[(size_t)cur * 32 + lane], acc);
            acc = make_float4(0.f, 0.f, 0.f, 0.f);
            cur = rj;
        }
        acc.x = fmaf(vj, xv.x, acc.x);
        acc.y = fmaf(vj, xv.y, acc.y);
        acc.z = fmaf(vj, xv.z, acc.z);
        acc.w = fmaf(vj, xv.w, acc.w);
    }
    atomicAdd(&nb4[(size_t)cur * 32 + lane], acc);
}

// ---------------------------------------------------------------------------
// K3 helpers
// ---------------------------------------------------------------------------
__device__ __forceinline__ uint32_t smem_u32(const void* p) {
    uint32_t a;
    asm("{ .reg .u64 t; cvta.to.shared.u64 t, %1; cvt.u32.u64 %0, t; }"
        : "=r"(a) : "l"(p));
    return a;
}
__device__ __forceinline__ uint32_t sw128(uint32_t off) {
    return off ^ ((off >> 3) & 0x70);
}
__device__ __forceinline__ void ldsm_x4(uint32_t& r0, uint32_t& r1,
                                        uint32_t& r2, uint32_t& r3, uint32_t a) {
    asm volatile("ldmatrix.sync.aligned.m8n8.x4.shared.b16 {%0,%1,%2,%3}, [%4];"
                 : "=r"(r0), "=r"(r1), "=r"(r2), "=r"(r3) : "r"(a));
}
__device__ __forceinline__ void ldsm_x2(uint32_t& r0, uint32_t& r1, uint32_t a) {
    asm volatile("ldmatrix.sync.aligned.m8n8.x2.shared.b16 {%0,%1}, [%2];"
                 : "=r"(r0), "=r"(r1) : "r"(a));
}
__device__ __forceinline__ void mma_bf16(float* c, const uint32_t* a,
                                         const uint32_t* b) {
    asm volatile(
        "mma.sync.aligned.m16n8k16.row.col.f32.bf16.bf16.f32 "
        "{%0,%1,%2,%3}, {%4,%5,%6,%7}, {%8,%9}, {%0,%1,%2,%3};"
        : "+f"(c[0]), "+f"(c[1]), "+f"(c[2]), "+f"(c[3])
        : "r"(a[0]), "r"(a[1]), "r"(a[2]), "r"(a[3]), "r"(b[0]), "r"(b[1]));
}

__device__ __forceinline__ void split_store(char* hi_base, char* lo_base,
                                            uint32_t sw_off, float4 v) {
    __nv_bfloat16 h0 = __float2bfloat16_rn(v.x);
    __nv_bfloat16 h1 = __float2bfloat16_rn(v.y);
    __nv_bfloat16 h2 = __float2bfloat16_rn(v.z);
    __nv_bfloat16 h3 = __float2bfloat16_rn(v.w);
    __nv_bfloat16 l0 = __float2bfloat16_rn(v.x - __bfloat162float(h0));
    __nv_bfloat16 l1 = __float2bfloat16_rn(v.y - __bfloat162float(h1));
    __nv_bfloat16 l2 = __float2bfloat16_rn(v.z - __bfloat162float(h2));
    __nv_bfloat16 l3 = __float2bfloat16_rn(v.w - __bfloat162float(h3));
    uint32_t hA = (uint32_t)__bfloat16_as_ushort(h0) | ((uint32_t)__bfloat16_as_ushort(h1) << 16);
    uint32_t hB = (uint32_t)__bfloat16_as_ushort(h2) | ((uint32_t)__bfloat16_as_ushort(h3) << 16);
    uint32_t lA = (uint32_t)__bfloat16_as_ushort(l0) | ((uint32_t)__bfloat16_as_ushort(l1) << 16);
    uint32_t lB = (uint32_t)__bfloat16_as_ushort(l2) | ((uint32_t)__bfloat16_as_ushort(l3) << 16);
    *reinterpret_cast<uint2*>(hi_base + sw_off) = make_uint2(hA, hB);
    *reinterpret_cast<uint2*>(lo_base + sw_off) = make_uint2(lA, lB);
}

// ---------------------------------------------------------------------------
// K3: bf16-split HMMA GEMM + bias + L2 normalize.
//   256 threads = 8 warps. CTA tile 128 rows x 128 cols. K in chunks of 64.
//   Warp tile 64x32: warp_m = wid&1 (rows), warp_n = wid>>1 (cols).
//   SMEM: Ahi/Alo/Whi/Wlo [128 x 64 bf16] = 128B rows, SW128 swizzled.
// ---------------------------------------------------------------------------
#define SM_BIAS 0
#define SM_RSS  512                 // float[4][128]
#define SM_AHI  4096
#define SM_ALO  (SM_AHI + 16384)
#define SM_WHI  (SM_ALO + 16384)
#define SM_WLO  (SM_WHI + 16384)
#define SM_TOTAL (SM_WLO + 16384)

__global__ void __launch_bounds__(256)
gemm_norm_kernel(const float* __restrict__ x,
                 const float* __restrict__ W,   // [128][256]
                 const float* __restrict__ b,   // [128]
                 float* __restrict__ out,
                 int N) {
    extern __shared__ char smem[];
    uint32_t sb = smem_u32(smem);
    float* bias = reinterpret_cast<float*>(smem + SM_BIAS);
    float (*rss)[128] = reinterpret_cast<float (*)[128]>(smem + SM_RSS);

    int t    = threadIdx.x;
    int wid  = t >> 5;
    int lane = t & 31;
    int warp_m = wid & 1;          // 0-1: rows  warp_m*64 .. +63
    int warp_n = wid >> 1;         // 0-3: cols  warp_n*32 .. +31
    int rowBase = blockIdx.x * 128;

    if (t < OUTF) bias[t] = __ldg(b + t);

    float acc[4][4][4];
    #pragma unroll
    for (int mi = 0; mi < 4; mi++)
        #pragma unroll
        for (int ni = 0; ni < 4; ni++)
            #pragma unroll
            for (int r = 0; r < 4; r++) acc[mi][ni][r] = 0.f;

    // ldmatrix lane addressing (byte offsets within a tile, before swizzle):
    // A frag (x4): row_local = lane&15, koff = (lane>>4)*8
    // B frag (x2): n_local = lane&7,  koff = ((lane>>3)&1)*8
    int aRow = warp_m * 64 + (lane & 15);
    int aK8  = (lane >> 4) * 8;          // 0 or 8
    int bRow = warp_n * 32 + (lane & 7);
    int bK8  = ((lane >> 3) & 1) * 8;

    for (int kc = 0; kc < TWOK; kc += 64) {
        const float* abase = (kc < INF) ? (x + kc) : (g_neighbor + (kc - INF));

        __syncthreads();   // previous chunk's compute done reading tiles

        // Stage 128 rows x 64 k of A and W as bf16 hi/lo (SW128, 128B rows)
        #pragma unroll
        for (int s = 0; s < 8; s++) {
            int i   = t + 256 * s;
            int row = i >> 4;
            int k4  = i & 15;
            int gr  = rowBase + row;
            float4 av = (gr < N)
                ? *reinterpret_cast<const float4*>(abase + (size_t)gr * INF + k4 * 4)
                : make_float4(0.f, 0.f, 0.f, 0.f);
            float4 wv = *reinterpret_cast<const float4*>(W + row * TWOK + kc + k4 * 4);
            uint32_t sw = sw128((uint32_t)(row * 128 + k4 * 8));
            split_store(smem + SM_AHI, smem + SM_ALO, sw, av);
            split_store(smem + SM_WHI, smem + SM_WLO, sw, wv);
        }
        __syncthreads();

        #pragma unroll
        for (int kk = 0; kk < 64; kk += 16) {
            uint32_t ahi[4][4], alo[4][4], bhi[4][2], blo[4][2];
            #pragma unroll
            for (int mi = 0; mi < 4; mi++) {
                uint32_t off = sw128((uint32_t)((aRow + mi * 16) * 128
                                                + (kk + aK8) * 2));
                ldsm_x4(ahi[mi][0], ahi[mi][1], ahi[mi][2], ahi[mi][3],
                        sb + SM_AHI + off);
                ldsm_x4(alo[mi][0], alo[mi][1], alo[mi][2], alo[mi][3],
                        sb + SM_ALO + off);
            }
            #pragma unroll
            for (int ni = 0; ni < 4; ni++) {
                uint32_t off = sw128((uint32_t)((bRow + ni * 8) * 128
                                                + (kk + bK8) * 2));
                ldsm_x2(bhi[ni][0], bhi[ni][1], sb + SM_WHI + off);
                ldsm_x2(blo[ni][0], blo[ni][1], sb + SM_WLO + off);
            }
            #pragma unroll
            for (int mi = 0; mi < 4; mi++)
                #pragma unroll
                for (int ni = 0; ni < 4; ni++) {
                    mma_bf16(acc[mi][ni], ahi[mi], bhi[ni]);
                    mma_bf16(acc[mi][ni], alo[mi], bhi[ni]);
                    mma_bf16(acc[mi][ni], ahi[mi], blo[ni]);
                }
        }
    }

    // ---- epilogue: bias, row sum-of-squares, normalize, store ----
    // c fragment: c0,c1 = (row lane/4,   col 2*(lane%4)+{0,1})
    //             c2,c3 = (row lane/4+8, col 2*(lane%4)+{0,1})
    int colBase = warp_n * 32 + 2 * (lane & 3);
    #pragma unroll
    for (int mi = 0; mi < 4; mi++)
        #pragma unroll
        for (int ni = 0; ni < 4; ni++) {
            float b0 = bias[colBase + ni * 8];
            float b1 = bias[colBase + ni * 8 + 1];
            acc[mi][ni][0] += b0;  acc[mi][ni][1] += b1;
            acc[mi][ni][2] += b0;  acc[mi][ni][3] += b1;
        }

    #pragma unroll
    for (int mi = 0; mi < 4; mi++) {
        #pragma unroll
        for (int half = 0; half < 2; half++) {
            float s = 0.f;
            #pragma unroll
            for (int ni = 0; ni < 4; ni++) {
                float c0 = acc[mi][ni][half * 2 + 0];
                float c1 = acc[mi][ni][half * 2 + 1];
                s = fmaf(c0, c0, s);
                s = fmaf(c1, c1, s);
            }
            s += __shfl_xor_sync(0xffffffffu, s, 1);
            s += __shfl_xor_sync(0xffffffffu, s, 2);
            if ((lane & 3) == 0)
                rss[warp_n][warp_m * 64 + mi * 16 + half * 8 + (lane >> 2)] = s;
        }
    }
    __syncthreads();

    float2* out2 = reinterpret_cast<float2*>(out);
    #pragma unroll
    for (int mi = 0; mi < 4; mi++) {
        #pragma unroll
        for (int half = 0; half < 2; half++) {
            int rl  = warp_m * 64 + mi * 16 + half * 8 + (lane >> 2);
            int row = rowBase + rl;
            if (row < N) {
                float ss = rss[0][rl] + rss[1][rl] + rss[2][rl] + rss[3][rl];
                float scale = 1.f / fmaxf(sqrtf(ss), 1e-12f);
                #pragma unroll
                for (int ni = 0; ni < 4; ni++) {
                    float2 o;
                    o.x = acc[mi][ni][half * 2 + 0] * scale;
                    o.y = acc[mi][ni][half * 2 + 1] * scale;
                    out2[(size_t)row * 64 + (colBase + ni * 8) / 2] = o;
                }
            }
        }
    }
}

// ---------------------------------------------------------------------------
// Launch
// ---------------------------------------------------------------------------
extern "C" void kernel_launch(void* const* d_in, const int* in_sizes, int n_in,
                              void* d_out, int out_size) {
    const float* x    = (const float*)d_in[0];
    const int*   rows = (const int*)  d_in[1];
    const int*   cols = (const int*)  d_in[2];
    const float* vals = (const float*)d_in[3];
    const float* W    = (const float*)d_in[4];
    const float* b    = (const float*)d_in[5];
    float*       out  = (float*)d_out;

    int N = in_sizes[0] / INF;
    int E = in_sizes[1];

    cudaFuncSetAttribute(gemm_norm_kernel,
                         cudaFuncAttributeMaxDynamicSharedMemorySize, SM_TOTAL);

    // K1: zero neighbor scratch
    int n4 = N * (INF / 4);
    zero_kernel<<<(n4 + 255) / 256, 256>>>(n4);

    // K2: SpMM
    int warps  = (E + 31) / 32;
    int blocks = (warps * 32 + 255) / 256;
    spmm_kernel<<<blocks, 256>>>(x, rows, cols, vals, E);

    // K3: HMMA GEMM + bias + normalize
    gemm_norm_kernel<<<(N + 127) / 128, 256, SM_TOTAL>>>(x, W, b, out, N);
}

// round 4
// speedup vs baseline: 2.0823x; 1.0752x over previous
#include <cuda_runtime.h>
#include <cuda_bf16.h>
#include <cstdint>

// ---------------------------------------------------------------------------
// GraphSAGE: out = normalize( [x | segsum(vals * x[cols])] @ W^T + b )
// N=100000, E=1600000, IN_F=OUT_F=128, rows sorted.
//
//   K1: zero neighbor scratch
//   K2: SpMM — coalesced edge loads + shfl broadcast; float4 atomic flush on
//       row change.
//   K0: W split precompute -> SW128-swizzled bf16 hi/lo smem images (once).
//   K3: HMMA bf16-split GEMM (Ahi*Bhi + Alo*Bhi + Ahi*Blo ~ fp32), W image
//       cp.async'd whole into smem, A double-buffered with reg prefetch,
//       fused bias + row L2-normalize.
// ---------------------------------------------------------------------------

#define NNODES   100000
#define INF      128
#define TWOK     256
#define OUTF     128

__device__ float g_neighbor[(size_t)NNODES * INF];
__device__ __align__(128) unsigned char g_Whi_img[65536];
__device__ __align__(128) unsigned char g_Wlo_img[65536];

// ---------------------------------------------------------------------------
// helpers
// ---------------------------------------------------------------------------
__device__ __forceinline__ uint32_t smem_u32(const void* p) {
    uint32_t a;
    asm("{ .reg .u64 t; cvta.to.shared.u64 t, %1; cvt.u32.u64 %0, t; }"
        : "=r"(a) : "l"(p));
    return a;
}
__device__ __forceinline__ uint32_t sw128(uint32_t off) {
    return off ^ ((off >> 3) & 0x70);
}
__device__ __forceinline__ void ldsm_x4(uint32_t& r0, uint32_t& r1,
                                        uint32_t& r2, uint32_t& r3, uint32_t a) {
    asm volatile("ldmatrix.sync.aligned.m8n8.x4.shared.b16 {%0,%1,%2,%3}, [%4];"
                 : "=r"(r0), "=r"(r1), "=r"(r2), "=r"(r3) : "r"(a));
}
__device__ __forceinline__ void ldsm_x2(uint32_t& r0, uint32_t& r1, uint32_t a) {
    asm volatile("ldmatrix.sync.aligned.m8n8.x2.shared.b16 {%0,%1}, [%2];"
                 : "=r"(r0), "=r"(r1) : "r"(a));
}
__device__ __forceinline__ void mma_bf16(float* c, const uint32_t* a,
                                         const uint32_t* b) {
    asm volatile(
        "mma.sync.aligned.m16n8k16.row.col.f32.bf16.bf16.f32 "
        "{%0,%1,%2,%3}, {%4,%5,%6,%7}, {%8,%9}, {%0,%1,%2,%3};"
        : "+f"(c[0]), "+f"(c[1]), "+f"(c[2]), "+f"(c[3])
        : "r"(a[0]), "r"(a[1]), "r"(a[2]), "r"(a[3]), "r"(b[0]), "r"(b[1]));
}
__device__ __forceinline__ void split_store(char* hi_base, char* lo_base,
                                            uint32_t sw_off, float4 v) {
    __nv_bfloat16 h0 = __float2bfloat16_rn(v.x);
    __nv_bfloat16 h1 = __float2bfloat16_rn(v.y);
    __nv_bfloat16 h2 = __float2bfloat16_rn(v.z);
    __nv_bfloat16 h3 = __float2bfloat16_rn(v.w);
    __nv_bfloat16 l0 = __float2bfloat16_rn(v.x - __bfloat162float(h0));
    __nv_bfloat16 l1 = __float2bfloat16_rn(v.y - __bfloat162float(h1));
    __nv_bfloat16 l2 = __float2bfloat16_rn(v.z - __bfloat162float(h2));
    __nv_bfloat16 l3 = __float2bfloat16_rn(v.w - __bfloat162float(h3));
    uint32_t hA = (uint32_t)__bfloat16_as_ushort(h0) | ((uint32_t)__bfloat16_as_ushort(h1) << 16);
    uint32_t hB = (uint32_t)__bfloat16_as_ushort(h2) | ((uint32_t)__bfloat16_as_ushort(h3) << 16);
    uint32_t lA = (uint32_t)__bfloat16_as_ushort(l0) | ((uint32_t)__bfloat16_as_ushort(l1) << 16);
    uint32_t lB = (uint32_t)__bfloat16_as_ushort(l2) | ((uint32_t)__bfloat16_as_ushort(l3) << 16);
    *reinterpret_cast<uint2*>(hi_base + sw_off) = make_uint2(hA, hB);
    *reinterpret_cast<uint2*>(lo_base + sw_off) = make_uint2(lA, lB);
}
#define CP_ASYNC16(dst, src) \
    asm volatile("cp.async.cg.shared.global [%0], [%1], 16;" :: "r"(dst), "l"(src))
#define CP_COMMIT() asm volatile("cp.async.commit_group;" ::: "memory")
#define CP_WAIT0()  asm volatile("cp.async.wait_group 0;" ::: "memory")

// ---------------------------------------------------------------------------
// K1: zero scratch
// ---------------------------------------------------------------------------
__global__ void zero_kernel(int n4) {
    int i = blockIdx.x * blockDim.x + threadIdx.x;
    if (i < n4)
        reinterpret_cast<float4*>(g_neighbor)[i] = make_float4(0.f, 0.f, 0.f, 0.f);
}

// ---------------------------------------------------------------------------
// K0: split W into SW128-swizzled bf16 hi/lo smem images.
// Image: [4 k-chunks][128 rows][64 bf16] (16KB per chunk), row = output col.
// ---------------------------------------------------------------------------
__global__ void wsplit_kernel(const float* __restrict__ W) {
    int i = blockIdx.x * blockDim.x + threadIdx.x;   // 0..8191 float4s
    int row   = i >> 6;
    int kf    = i & 63;
    int chunk = kf >> 4;
    int k4    = kf & 15;
    float4 wv = *reinterpret_cast<const float4*>(W + row * TWOK + chunk * 64 + k4 * 4);
    uint32_t off = chunk * 16384 + sw128((uint32_t)(row * 128 + k4 * 8));
    split_store((char*)g_Whi_img, (char*)g_Wlo_img, off, wv);
}

// ---------------------------------------------------------------------------
// K2: SpMM. Warp handles 32 edges: lane l loads edge (base+l) coalesced,
// then 32 shfl-broadcast steps; lane owns feature dims [4l, 4l+4).
// ---------------------------------------------------------------------------
__global__ void spmm_kernel(const float* __restrict__ x,
                            const int*   __restrict__ rows,
                            const int*   __restrict__ cols,
                            const float* __restrict__ vals,
                            int E) {
    int warp = (blockIdx.x * blockDim.x + threadIdx.x) >> 5;
    int lane = threadIdx.x & 31;
    long base = (long)warp * 32;
    if (base >= E) return;

    long e = base + lane;
    bool valid = e < E;
    long es = valid ? e : (long)E - 1;
    int   r = __ldg(rows + es);
    int   c = valid ? __ldg(cols + e) : 0;
    float v = valid ? __ldg(vals + e) : 0.f;

    const float4* x4  = reinterpret_cast<const float4*>(x);
    float4*       nb4 = reinterpret_cast<float4*>(g_neighbor);

    int cur = __shfl_sync(0xffffffffu, r, 0);
    float4 acc = make_float4(0.f, 0.f, 0.f, 0.f);

    #pragma unroll
    for (int j = 0; j < 32; j++) {
        int   rj = __shfl_sync(0xffffffffu, r, j);
        int   cj = __shfl_sync(0xffffffffu, c, j);
        float vj = __shfl_sync(0xffffffffu, v, j);
        float4 xv = x4[(size_t)cj * 32 + lane];
        if (rj != cur) {                       // warp-uniform
            atomicAdd(&nb4[(size_t)cur * 32 + lane], acc);
            acc = make_float4(0.f, 0.f, 0.f, 0.f);
            cur = rj;
        }
        acc.x = fmaf(vj, xv.x, acc.x);
        acc.y = fmaf(vj, xv.y, acc.y);
        acc.z = fmaf(vj, xv.z, acc.z);
        acc.w = fmaf(vj, xv.w, acc.w);
    }
    atomicAdd(&nb4[(size_t)cur * 32 + lane], acc);
}

// ---------------------------------------------------------------------------
// K3: bf16-split HMMA GEMM + bias + L2 normalize.
//   256 threads = 8 warps. CTA tile 128 rows x 128 cols, K=256 in 4 chunks.
//   W (full, hi+lo) resident in smem via cp.async of precomputed image.
//   A double-buffered, reg-prefetch pipeline, 1 barrier per chunk.
// ---------------------------------------------------------------------------
#define SM_BIAS 0
#define SM_RSS  512                  // float[4][128]
#define SM_WHI  4096                 // 65536 (4 chunk images)
#define SM_WLO  (SM_WHI + 65536)     // 65536
#define SM_A    (SM_WLO + 65536)     // 2 stages x (16KB hi + 16KB lo)
#define SM_TOTAL (SM_A + 65536)

__global__ void __launch_bounds__(256)
gemm_norm_kernel(const float* __restrict__ x,
                 const float* __restrict__ b,
                 float* __restrict__ out,
                 int N) {
    extern __shared__ char smem[];
    uint32_t sb = smem_u32(smem);
    float* bias = reinterpret_cast<float*>(smem + SM_BIAS);
    float (*rss)[128] = reinterpret_cast<float (*)[128]>(smem + SM_RSS);

    int t    = threadIdx.x;
    int wid  = t >> 5;
    int lane = t & 31;
    int warp_m = wid & 1;
    int warp_n = wid >> 1;
    int rowBase = blockIdx.x * 128;

    // W image -> smem (async, overlapped with A stage below)
    #pragma unroll
    for (int j = 0; j < 16; j++) {
        CP_ASYNC16(sb + SM_WHI + t * 16 + j * 4096, g_Whi_img + t * 16 + j * 4096);
        CP_ASYNC16(sb + SM_WLO + t * 16 + j * 4096, g_Wlo_img + t * 16 + j * 4096);
    }
    CP_COMMIT();

    if (t < OUTF) bias[t] = __ldg(b + t);

    // A staging geometry: thread covers (row = t>>4 + 16s, k4 = t&15), s<8
    int sRow = t >> 4;
    int sK4  = t & 15;

    float4 pref[8];
    // stage chunk 0
    {
        const float* abase = x;  // chunk 0: k 0..63 of x
        #pragma unroll
        for (int s = 0; s < 8; s++) {
            int gr = rowBase + sRow + 16 * s;
            pref[s] = (gr < N)
                ? *reinterpret_cast<const float4*>(abase + (size_t)gr * INF + sK4 * 4)
                : make_float4(0.f, 0.f, 0.f, 0.f);
        }
        #pragma unroll
        for (int s = 0; s < 8; s++) {
            uint32_t sw = sw128((uint32_t)((sRow + 16 * s) * 128 + sK4 * 8));
            split_store(smem + SM_A, smem + SM_A + 16384, sw, pref[s]);
        }
    }
    CP_WAIT0();
    __syncthreads();

    float acc[4][4][4];
    #pragma unroll
    for (int mi = 0; mi < 4; mi++)
        #pragma unroll
        for (int ni = 0; ni < 4; ni++)
            #pragma unroll
            for (int r = 0; r < 4; r++) acc[mi][ni][r] = 0.f;

    int aRow = warp_m * 64 + (lane & 15);
    int aK8  = (lane >> 4) * 8;
    int bRow = warp_n * 32 + (lane & 7);
    int bK8  = ((lane >> 3) & 1) * 8;

    #pragma unroll
    for (int c = 0; c < 4; c++) {
        // prefetch next chunk
        if (c < 3) {
            const float* abase = (c + 1 < 2) ? (x + (c + 1) * 64)
                                             : (g_neighbor + (c - 1) * 64);
            #pragma unroll
            for (int s = 0; s < 8; s++) {
                int gr = rowBase + sRow + 16 * s;
                pref[s] = (gr < N)
                    ? *reinterpret_cast<const float4*>(abase + (size_t)gr * INF + sK4 * 4)
                    : make_float4(0.f, 0.f, 0.f, 0.f);
            }
        }

        uint32_t aBuf = sb + SM_A + (c & 1) * 32768;
        uint32_t wBase = c * 16384;
        #pragma unroll
        for (int kk = 0; kk < 64; kk += 16) {
            uint32_t ahi[4][4], alo[4][4], bhi[4][2], blo[4][2];
            #pragma unroll
            for (int mi = 0; mi < 4; mi++) {
                uint32_t off = sw128((uint32_t)((aRow + mi * 16) * 128
                                                + (kk + aK8) * 2));
                ldsm_x4(ahi[mi][0], ahi[mi][1], ahi[mi][2], ahi[mi][3], aBuf + off);
                ldsm_x4(alo[mi][0], alo[mi][1], alo[mi][2], alo[mi][3],
                        aBuf + 16384 + off);
            }
            #pragma unroll
            for (int ni = 0; ni < 4; ni++) {
                uint32_t off = sw128((uint32_t)((bRow + ni * 8) * 128
                                                + (kk + bK8) * 2));
                ldsm_x2(bhi[ni][0], bhi[ni][1], sb + SM_WHI + wBase + off);
                ldsm_x2(blo[ni][0], blo[ni][1], sb + SM_WLO + wBase + off);
            }
            #pragma unroll
            for (int mi = 0; mi < 4; mi++)
                #pragma unroll
                for (int ni = 0; ni < 4; ni++) {
                    mma_bf16(acc[mi][ni], ahi[mi], bhi[ni]);
                    mma_bf16(acc[mi][ni], alo[mi], bhi[ni]);
                    mma_bf16(acc[mi][ni], ahi[mi], blo[ni]);
                }
        }

        if (c < 3) {
            char* dst = smem + SM_A + ((c + 1) & 1) * 32768;
            #pragma unroll
            for (int s = 0; s < 8; s++) {
                uint32_t sw = sw128((uint32_t)((sRow + 16 * s) * 128 + sK4 * 8));
                split_store(dst, dst + 16384, sw, pref[s]);
            }
            __syncthreads();
        }
    }

    // ---- epilogue: bias, row sum-of-squares, normalize, store ----
    int colBase = warp_n * 32 + 2 * (lane & 3);
    #pragma unroll
    for (int mi = 0; mi < 4; mi++)
        #pragma unroll
        for (int ni = 0; ni < 4; ni++) {
            float b0 = bias[colBase + ni * 8];
            float b1 = bias[colBase + ni * 8 + 1];
            acc[mi][ni][0] += b0;  acc[mi][ni][1] += b1;
            acc[mi][ni][2] += b0;  acc[mi][ni][3] += b1;
        }

    #pragma unroll
    for (int mi = 0; mi < 4; mi++) {
        #pragma unroll
        for (int half = 0; half < 2; half++) {
            float s = 0.f;
            #pragma unroll
            for (int ni = 0; ni < 4; ni++) {
                float c0 = acc[mi][ni][half * 2 + 0];
                float c1 = acc[mi][ni][half * 2 + 1];
                s = fmaf(c0, c0, s);
                s = fmaf(c1, c1, s);
            }
            s += __shfl_xor_sync(0xffffffffu, s, 1);
            s += __shfl_xor_sync(0xffffffffu, s, 2);
            if ((lane & 3) == 0)
                rss[warp_n][warp_m * 64 + mi * 16 + half * 8 + (lane >> 2)] = s;
        }
    }
    __syncthreads();

    float2* out2 = reinterpret_cast<float2*>(out);
    #pragma unroll
    for (int mi = 0; mi < 4; mi++) {
        #pragma unroll
        for (int half = 0; half < 2; half++) {
            int rl  = warp_m * 64 + mi * 16 + half * 8 + (lane >> 2);
            int row = rowBase + rl;
            if (row < N) {
                float ss = rss[0][rl] + rss[1][rl] + rss[2][rl] + rss[3][rl];
                float scale = 1.f / fmaxf(sqrtf(ss), 1e-12f);
                #pragma unroll
                for (int ni = 0; ni < 4; ni++) {
                    float2 o;
                    o.x = acc[mi][ni][half * 2 + 0] * scale;
                    o.y = acc[mi][ni][half * 2 + 1] * scale;
                    out2[(size_t)row * 64 + (colBase + ni * 8) / 2] = o;
                }
            }
        }
    }
}

// ---------------------------------------------------------------------------
// Launch
// ---------------------------------------------------------------------------
extern "C" void kernel_launch(void* const* d_in, const int* in_sizes, int n_in,
                              void* d_out, int out_size) {
    const float* x    = (const float*)d_in[0];
    const int*   rows = (const int*)  d_in[1];
    const int*   cols = (const int*)  d_in[2];
    const float* vals = (const float*)d_in[3];
    const float* W    = (const float*)d_in[4];
    const float* b    = (const float*)d_in[5];
    float*       out  = (float*)d_out;

    int N = in_sizes[0] / INF;
    int E = in_sizes[1];

    cudaFuncSetAttribute(gemm_norm_kernel,
                         cudaFuncAttributeMaxDynamicSharedMemorySize, SM_TOTAL);

    // K0: W split (independent of SpMM result)
    wsplit_kernel<<<32, 256>>>(W);

    // K1: zero neighbor scratch
    int n4 = N * (INF / 4);
    zero_kernel<<<(n4 + 255) / 256, 256>>>(n4);

    // K2: SpMM
    int warps  = (E + 31) / 32;
    int blocks = (warps * 32 + 255) / 256;
    spmm_kernel<<<blocks, 256>>>(x, rows, cols, vals, E);

    // K3: HMMA GEMM + bias + normalize
    gemm_norm_kernel<<<(N + 127) / 128, 256, SM_TOTAL>>>(x, b, out, N);
}

// round 5
// speedup vs baseline: 2.3822x; 1.1441x over previous
#include <cuda_runtime.h>
#include <cuda_bf16.h>
#include <cstdint>

// ---------------------------------------------------------------------------
// GraphSAGE: out = normalize( [x | segsum(vals * x[cols])] @ W^T + b )
// N=100000, E=1600000, IN_F=OUT_F=128, rows sorted.
//
//   K0: W split -> SW128-swizzled bf16 hi/lo images (once).
//   K1: zero neighbor scratch
//   K2: SpMM — coalesced edge loads + shfl broadcast; float4 atomic flush.
//   K3: HMMA bf16-split GEMM, 512 threads / 16 warps (latency fix: was 8
//       warps @ 255 regs -> tensor pipe 33.8%). W resident in smem, A
//       double-buffered, fused bias + row L2-normalize.
// ---------------------------------------------------------------------------

#define NNODES   100000
#define INF      128
#define TWOK     256
#define OUTF     128

__device__ float g_neighbor[(size_t)NNODES * INF];
__device__ __align__(128) unsigned char g_Whi_img[65536];
__device__ __align__(128) unsigned char g_Wlo_img[65536];

// ---------------------------------------------------------------------------
// helpers
// ---------------------------------------------------------------------------
__device__ __forceinline__ uint32_t smem_u32(const void* p) {
    uint32_t a;
    asm("{ .reg .u64 t; cvta.to.shared.u64 t, %1; cvt.u32.u64 %0, t; }"
        : "=r"(a) : "l"(p));
    return a;
}
__device__ __forceinline__ uint32_t sw128(uint32_t off) {
    return off ^ ((off >> 3) & 0x70);
}
__device__ __forceinline__ void ldsm_x4(uint32_t& r0, uint32_t& r1,
                                        uint32_t& r2, uint32_t& r3, uint32_t a) {
    asm volatile("ldmatrix.sync.aligned.m8n8.x4.shared.b16 {%0,%1,%2,%3}, [%4];"
                 : "=r"(r0), "=r"(r1), "=r"(r2), "=r"(r3) : "r"(a));
}
__device__ __forceinline__ void ldsm_x2(uint32_t& r0, uint32_t& r1, uint32_t a) {
    asm volatile("ldmatrix.sync.aligned.m8n8.x2.shared.b16 {%0,%1}, [%2];"
                 : "=r"(r0), "=r"(r1) : "r"(a));
}
__device__ __forceinline__ void mma_bf16(float* c, const uint32_t* a,
                                         const uint32_t* b) {
    asm volatile(
        "mma.sync.aligned.m16n8k16.row.col.f32.bf16.bf16.f32 "
        "{%0,%1,%2,%3}, {%4,%5,%6,%7}, {%8,%9}, {%0,%1,%2,%3};"
        : "+f"(c[0]), "+f"(c[1]), "+f"(c[2]), "+f"(c[3])
        : "r"(a[0]), "r"(a[1]), "r"(a[2]), "r"(a[3]), "r"(b[0]), "r"(b[1]));
}
__device__ __forceinline__ void split_store(char* hi_base, char* lo_base,
                                            uint32_t sw_off, float4 v) {
    __nv_bfloat16 h0 = __float2bfloat16_rn(v.x);
    __nv_bfloat16 h1 = __float2bfloat16_rn(v.y);
    __nv_bfloat16 h2 = __float2bfloat16_rn(v.z);
    __nv_bfloat16 h3 = __float2bfloat16_rn(v.w);
    __nv_bfloat16 l0 = __float2bfloat16_rn(v.x - __bfloat162float(h0));
    __nv_bfloat16 l1 = __float2bfloat16_rn(v.y - __bfloat162float(h1));
    __nv_bfloat16 l2 = __float2bfloat16_rn(v.z - __bfloat162float(h2));
    __nv_bfloat16 l3 = __float2bfloat16_rn(v.w - __bfloat162float(h3));
    uint32_t hA = (uint32_t)__bfloat16_as_ushort(h0) | ((uint32_t)__bfloat16_as_ushort(h1) << 16);
    uint32_t hB = (uint32_t)__bfloat16_as_ushort(h2) | ((uint32_t)__bfloat16_as_ushort(h3) << 16);
    uint32_t lA = (uint32_t)__bfloat16_as_ushort(l0) | ((uint32_t)__bfloat16_as_ushort(l1) << 16);
    uint32_t lB = (uint32_t)__bfloat16_as_ushort(l2) | ((uint32_t)__bfloat16_as_ushort(l3) << 16);
    *reinterpret_cast<uint2*>(hi_base + sw_off) = make_uint2(hA, hB);
    *reinterpret_cast<uint2*>(lo_base + sw_off) = make_uint2(lA, lB);
}
#define CP_ASYNC16(dst, src) \
    asm volatile("cp.async.cg.shared.global [%0], [%1], 16;" :: "r"(dst), "l"(src))
#define CP_COMMIT() asm volatile("cp.async.commit_group;" ::: "memory")
#define CP_WAIT0()  asm volatile("cp.async.wait_group 0;" ::: "memory")

// ---------------------------------------------------------------------------
// K1: zero scratch
// ---------------------------------------------------------------------------
__global__ void zero_kernel(int n4) {
    int i = blockIdx.x * blockDim.x + threadIdx.x;
    if (i < n4)
        reinterpret_cast<float4*>(g_neighbor)[i] = make_float4(0.f, 0.f, 0.f, 0.f);
}

// ---------------------------------------------------------------------------
// K0: split W into SW128-swizzled bf16 hi/lo images.
// Image: [4 k-chunks][128 rows][64 bf16] (16KB per chunk), row = output col.
// ---------------------------------------------------------------------------
__global__ void wsplit_kernel(const float* __restrict__ W) {
    int i = blockIdx.x * blockDim.x + threadIdx.x;   // 0..8191 float4s
    int row   = i >> 6;
    int kf    = i & 63;
    int chunk = kf >> 4;
    int k4    = kf & 15;
    float4 wv = *reinterpret_cast<const float4*>(W + row * TWOK + chunk * 64 + k4 * 4);
    uint32_t off = chunk * 16384 + sw128((uint32_t)(row * 128 + k4 * 8));
    split_store((char*)g_Whi_img, (char*)g_Wlo_img, off, wv);
}

// ---------------------------------------------------------------------------
// K2: SpMM. Warp handles 32 edges: lane l loads edge (base+l) coalesced,
// then 32 shfl-broadcast steps; lane owns feature dims [4l, 4l+4).
// ---------------------------------------------------------------------------
__global__ void spmm_kernel(const float* __restrict__ x,
                            const int*   __restrict__ rows,
                            const int*   __restrict__ cols,
                            const float* __restrict__ vals,
                            int E) {
    int warp = (blockIdx.x * blockDim.x + threadIdx.x) >> 5;
    int lane = threadIdx.x & 31;
    long base = (long)warp * 32;
    if (base >= E) return;

    long e = base + lane;
    bool valid = e < E;
    long es = valid ? e : (long)E - 1;
    int   r = __ldg(rows + es);
    int   c = valid ? __ldg(cols + e) : 0;
    float v = valid ? __ldg(vals + e) : 0.f;

    const float4* x4  = reinterpret_cast<const float4*>(x);
    float4*       nb4 = reinterpret_cast<float4*>(g_neighbor);

    int cur = __shfl_sync(0xffffffffu, r, 0);
    float4 acc = make_float4(0.f, 0.f, 0.f, 0.f);

    #pragma unroll
    for (int j = 0; j < 32; j++) {
        int   rj = __shfl_sync(0xffffffffu, r, j);
        int   cj = __shfl_sync(0xffffffffu, c, j);
        float vj = __shfl_sync(0xffffffffu, v, j);
        float4 xv = x4[(size_t)cj * 32 + lane];
        if (rj != cur) {                       // warp-uniform
            atomicAdd(&nb4[(size_t)cur * 32 + lane], acc);
            acc = make_float4(0.f, 0.f, 0.f, 0.f);
            cur = rj;
        }
        acc.x = fmaf(vj, xv.x, acc.x);
        acc.y = fmaf(vj, xv.y, acc.y);
        acc.z = fmaf(vj, xv.z, acc.z);
        acc.w = fmaf(vj, xv.w, acc.w);
    }
    atomicAdd(&nb4[(size_t)cur * 32 + lane], acc);
}

// ---------------------------------------------------------------------------
// K3: bf16-split HMMA GEMM + bias + L2 normalize.
//   512 threads = 16 warps. CTA tile 128x128, warp tile 32x32 (mi2 x ni4).
//   warp_m = wid&3 (rows), warp_n = wid>>2 (cols). K=256 in 4 chunks of 64.
//   W (hi+lo, all chunks) resident in smem; A double-buffered, reg prefetch.
// ---------------------------------------------------------------------------
#define SM_BIAS 0
#define SM_RSS  512                  // float[4][128]
#define SM_WHI  4096                 // 65536
#define SM_WLO  (SM_WHI + 65536)     // 65536
#define SM_A    (SM_WLO + 65536)     // 2 stages x (16KB hi + 16KB lo)
#define SM_TOTAL (SM_A + 65536)

__global__ void __launch_bounds__(512, 1)
gemm_norm_kernel(const float* __restrict__ x,
                 const float* __restrict__ b,
                 float* __restrict__ out,
                 int N) {
    extern __shared__ char smem[];
    uint32_t sb = smem_u32(smem);
    float* bias = reinterpret_cast<float*>(smem + SM_BIAS);
    float (*rss)[128] = reinterpret_cast<float (*)[128]>(smem + SM_RSS);

    int t    = threadIdx.x;
    int wid  = t >> 5;
    int lane = t & 31;
    int warp_m = wid & 3;          // rows warp_m*32 .. +31
    int warp_n = wid >> 2;         // cols warp_n*32 .. +31
    int rowBase = blockIdx.x * 128;

    // W image -> smem (async)
    #pragma unroll
    for (int j = 0; j < 8; j++) {
        CP_ASYNC16(sb + SM_WHI + t * 16 + j * 8192, g_Whi_img + t * 16 + j * 8192);
        CP_ASYNC16(sb + SM_WLO + t * 16 + j * 8192, g_Wlo_img + t * 16 + j * 8192);
    }
    CP_COMMIT();

    if (t < OUTF) bias[t] = __ldg(b + t);

    // A staging geometry: thread covers (row = (t>>4) + 32s, k4 = t&15), s<4
    int sRow = t >> 4;
    int sK4  = t & 15;

    float4 pref[4];
    {
        const float* abase = x;
        #pragma unroll
        for (int s = 0; s < 4; s++) {
            int gr = rowBase + sRow + 32 * s;
            pref[s] = (gr < N)
                ? *reinterpret_cast<const float4*>(abase + (size_t)gr * INF + sK4 * 4)
                : make_float4(0.f, 0.f, 0.f, 0.f);
        }
        #pragma unroll
        for (int s = 0; s < 4; s++) {
            uint32_t sw = sw128((uint32_t)((sRow + 32 * s) * 128 + sK4 * 8));
            split_store(smem + SM_A, smem + SM_A + 16384, sw, pref[s]);
        }
    }
    CP_WAIT0();
    __syncthreads();

    float acc[2][4][4];
    #pragma unroll
    for (int mi = 0; mi < 2; mi++)
        #pragma unroll
        for (int ni = 0; ni < 4; ni++)
            #pragma unroll
            for (int r = 0; r < 4; r++) acc[mi][ni][r] = 0.f;

    int aRow = warp_m * 32 + (lane & 15);
    int aK8  = (lane >> 4) * 8;
    int bRow = warp_n * 32 + (lane & 7);
    int bK8  = ((lane >> 3) & 1) * 8;

    #pragma unroll
    for (int c = 0; c < 4; c++) {
        if (c < 3) {
            const float* abase = (c + 1 < 2) ? (x + (c + 1) * 64)
                                             : (g_neighbor + (c - 1) * 64);
            #pragma unroll
            for (int s = 0; s < 4; s++) {
                int gr = rowBase + sRow + 32 * s;
                pref[s] = (gr < N)
                    ? *reinterpret_cast<const float4*>(abase + (size_t)gr * INF + sK4 * 4)
                    : make_float4(0.f, 0.f, 0.f, 0.f);
            }
        }

        uint32_t aBuf = sb + SM_A + (c & 1) * 32768;
        uint32_t wBase = c * 16384;
        #pragma unroll
        for (int kk = 0; kk < 64; kk += 16) {
            uint32_t ahi[2][4], alo[2][4], bhi[4][2], blo[4][2];
            #pragma unroll
            for (int mi = 0; mi < 2; mi++) {
                uint32_t off = sw128((uint32_t)((aRow + mi * 16) * 128
                                                + (kk + aK8) * 2));
                ldsm_x4(ahi[mi][0], ahi[mi][1], ahi[mi][2], ahi[mi][3], aBuf + off);
                ldsm_x4(alo[mi][0], alo[mi][1], alo[mi][2], alo[mi][3],
                        aBuf + 16384 + off);
            }
            #pragma unroll
            for (int ni = 0; ni < 4; ni++) {
                uint32_t off = sw128((uint32_t)((bRow + ni * 8) * 128
                                                + (kk + bK8) * 2));
                ldsm_x2(bhi[ni][0], bhi[ni][1], sb + SM_WHI + wBase + off);
                ldsm_x2(blo[ni][0], blo[ni][1], sb + SM_WLO + wBase + off);
            }
            #pragma unroll
            for (int mi = 0; mi < 2; mi++)
                #pragma unroll
                for (int ni = 0; ni < 4; ni++) {
                    mma_bf16(acc[mi][ni], ahi[mi], bhi[ni]);
                    mma_bf16(acc[mi][ni], alo[mi], bhi[ni]);
                    mma_bf16(acc[mi][ni], ahi[mi], blo[ni]);
                }
        }

        if (c < 3) {
            char* dst = smem + SM_A + ((c + 1) & 1) * 32768;
            #pragma unroll
            for (int s = 0; s < 4; s++) {
                uint32_t sw = sw128((uint32_t)((sRow + 32 * s) * 128 + sK4 * 8));
                split_store(dst, dst + 16384, sw, pref[s]);
            }
            __syncthreads();
        }
    }

    // ---- epilogue: bias, row sum-of-squares, normalize, store ----
    int colBase = warp_n * 32 + 2 * (lane & 3);
    #pragma unroll
    for (int mi = 0; mi < 2; mi++)
        #pragma unroll
        for (int ni = 0; ni < 4; ni++) {
            float b0 = bias[colBase + ni * 8];
            float b1 = bias[colBase + ni * 8 + 1];
            acc[mi][ni][0] += b0;  acc[mi][ni][1] += b1;
            acc[mi][ni][2] += b0;  acc[mi][ni][3] += b1;
        }

    #pragma unroll
    for (int mi = 0; mi < 2; mi++) {
        #pragma unroll
        for (int half = 0; half < 2; half++) {
            float s = 0.f;
            #pragma unroll
            for (int ni = 0; ni < 4; ni++) {
                float c0 = acc[mi][ni][half * 2 + 0];
                float c1 = acc[mi][ni][half * 2 + 1];
                s = fmaf(c0, c0, s);
                s = fmaf(c1, c1, s);
            }
            s += __shfl_xor_sync(0xffffffffu, s, 1);
            s += __shfl_xor_sync(0xffffffffu, s, 2);
            if ((lane & 3) == 0)
                rss[warp_n][warp_m * 32 + mi * 16 + half * 8 + (lane >> 2)] = s;
        }
    }
    __syncthreads();

    float2* out2 = reinterpret_cast<float2*>(out);
    #pragma unroll
    for (int mi = 0; mi < 2; mi++) {
        #pragma unroll
        for (int half = 0; half < 2; half++) {
            int rl  = warp_m * 32 + mi * 16 + half * 8 + (lane >> 2);
            int row = rowBase + rl;
            if (row < N) {
                float ss = rss[0][rl] + rss[1][rl] + rss[2][rl] + rss[3][rl];
                float scale = 1.f / fmaxf(sqrtf(ss), 1e-12f);
                #pragma unroll
                for (int ni = 0; ni < 4; ni++) {
                    float2 o;
                    o.x = acc[mi][ni][half * 2 + 0] * scale;
                    o.y = acc[mi][ni][half * 2 + 1] * scale;
                    out2[(size_t)row * 64 + (colBase + ni * 8) / 2] = o;
                }
            }
        }
    }
}

// ---------------------------------------------------------------------------
// Launch
// ---------------------------------------------------------------------------
extern "C" void kernel_launch(void* const* d_in, const int* in_sizes, int n_in,
                              void* d_out, int out_size) {
    const float* x    = (const float*)d_in[0];
    const int*   rows = (const int*)  d_in[1];
    const int*   cols = (const int*)  d_in[2];
    const float* vals = (const float*)d_in[3];
    const float* W    = (const float*)d_in[4];
    const float* b    = (const float*)d_in[5];
    float*       out  = (float*)d_out;

    int N = in_sizes[0] / INF;
    int E = in_sizes[1];

    cudaFuncSetAttribute(gemm_norm_kernel,
                         cudaFuncAttributeMaxDynamicSharedMemorySize, SM_TOTAL);

    // K0: W split (independent of SpMM result)
    wsplit_kernel<<<32, 256>>>(W);

    // K1: zero neighbor scratch
    int n4 = N * (INF / 4);
    zero_kernel<<<(n4 + 255) / 256, 256>>>(n4);

    // K2: SpMM
    int warps  = (E + 31) / 32;
    int blocks = (warps * 32 + 255) / 256;
    spmm_kernel<<<blocks, 256>>>(x, rows, cols, vals, E);

    // K3: HMMA GEMM + bias + normalize
    gemm_norm_kernel<<<(N + 127) / 128, 512, SM_TOTAL>>>(x, b, out, N);
}